// round 16
// baseline (speedup 1.0000x reference)
#include <cuda_runtime.h>
#include <cuda_fp16.h>
#include <cstdint>

// ---------------------------------------------------------------------------
// SketchLinear — converged kernel (session best, reproduced 3x at ~199.2us)
//   1) sketch: countsketch both tensors, 2 rows/block, packed f16x2 shared
//      atomics, fp32->fp16 output panels.
//   2) gemm:   C = A * B^T + bias via mma.sync.m16n8k16 (fp16 in, fp32 acc),
//      BM=BN=128, BK=64, 2-stage cp.async, 8 warps (4Mx2N), 2 CTAs/SM.
// ---------------------------------------------------------------------------
#define BROWS 4096
#define DDIM  4096
#define OROWS 4096
#define MBUCK 2048

#define GM 4096
#define GN 4096
#define GK 2048
#define BM 128
#define BN 128
#define BK 64
#define NKT (GK / BK)      // 32

#define A_TILE_B 16384
#define STAGE_B  32768
#define SMEM_TOTAL (2 * STAGE_B)

__device__ __align__(16) __half g_A[(size_t)GM * GK];  // 16 MB
__device__ __align__(16) __half g_B[(size_t)GN * GK];  // 16 MB

// ---------------------------------------------------------------------------
// Sketch kernel: 2 rows per block, packed f16x2 shared atomics.
// blocks [0,2048) -> input row-pairs -> g_A, [2048,4096) -> weight -> g_B.
// Interleaved load/atomic issue (explicit MLP front-batching regresses via
// cross-CTA L1tex-queue contention; gather/CSR and row-batching also slower).
// ---------------------------------------------------------------------------
__global__ __launch_bounds__(256) void sketch_kernel(
    const float* __restrict__ inA,
    const float* __restrict__ inB,
    const int*   __restrict__ hidx,
    const float* __restrict__ sgn)
{
    __shared__ __align__(16) __half2 acc[MBUCK];
    const int which = blockIdx.x >> 11;            // 0 -> A, 1 -> B
    const int row0  = (blockIdx.x & 2047) * 2;
    const float* x  = which ? inB : inA;
    const int tid = threadIdx.x;

    const float4* xr0 = (const float4*)(x + (size_t)row0 * DDIM);
    const float4* xr1 = (const float4*)(x + (size_t)(row0 + 1) * DDIM);
    const int4*   h4  = (const int4*)hidx;
    const float4* s4  = (const float4*)sgn;

    for (int i = tid; i < MBUCK; i += 256)
        acc[i] = __halves2half2(__float2half(0.0f), __float2half(0.0f));
    __syncthreads();

    #pragma unroll
    for (int it = 0; it < DDIM / 4 / 256; ++it) {   // 4 iters
        const int idx = it * 256 + tid;
        const float4 a  = xr0[idx];
        const float4 b  = xr1[idx];
        const int4   hv = h4[idx];
        const float4 sv = s4[idx];
        atomicAdd(&acc[hv.x], __floats2half2_rn(a.x * sv.x, b.x * sv.x));
        atomicAdd(&acc[hv.y], __floats2half2_rn(a.y * sv.y, b.y * sv.y));
        atomicAdd(&acc[hv.z], __floats2half2_rn(a.z * sv.z, b.z * sv.z));
        atomicAdd(&acc[hv.w], __floats2half2_rn(a.w * sv.w, b.w * sv.w));
    }
    __syncthreads();

    const int k0 = tid * 8;
    uint32_t r0w[4], r1w[4];
    #pragma unroll
    for (int j = 0; j < 4; ++j) {
        const __half2 p0 = acc[k0 + 2 * j];
        const __half2 p1 = acc[k0 + 2 * j + 1];
        __half2 q0 = __halves2half2(__low2half(p0),  __low2half(p1));   // row0
        __half2 q1 = __halves2half2(__high2half(p0), __high2half(p1));  // row1
        r0w[j] = *(uint32_t*)&q0;
        r1w[j] = *(uint32_t*)&q1;
    }
    __half* pan = which ? g_B : g_A;
    *(uint4*)(pan + (size_t)row0 * GK + k0)       = make_uint4(r0w[0], r0w[1], r0w[2], r0w[3]);
    *(uint4*)(pan + (size_t)(row0 + 1) * GK + k0) = make_uint4(r1w[0], r1w[1], r1w[2], r1w[3]);
}

// ---------------------------------------------------------------------------
// GEMM helpers
// ---------------------------------------------------------------------------
__device__ __forceinline__ uint32_t sm_u32(const void* p) {
    uint32_t r;
    asm("{ .reg .u64 t; cvta.to.shared.u64 t, %1; cvt.u32.u64 %0, t; }"
        : "=r"(r) : "l"(p));
    return r;
}

#define CP_ASYNC16(saddr, gaddr) \
    asm volatile("cp.async.cg.shared.global.L2::256B [%0], [%1], 16;" \
                 :: "r"(saddr), "l"(gaddr))
#define CP_COMMIT() asm volatile("cp.async.commit_group;")
#define CP_WAIT(n)  asm volatile("cp.async.wait_group %0;" :: "n"(n))

#define LDMATRIX_X4(r0, r1, r2, r3, addr) \
    asm volatile("ldmatrix.sync.aligned.m8n8.x4.shared.b16 {%0,%1,%2,%3}, [%4];" \
                 : "=r"(r0), "=r"(r1), "=r"(r2), "=r"(r3) : "r"(addr))

#define MMA_16816(d, a, b) \
    asm volatile("mma.sync.aligned.m16n8k16.row.col.f32.f16.f16.f32 " \
                 "{%0,%1,%2,%3}, {%4,%5,%6,%7}, {%8,%9}, {%0,%1,%2,%3};" \
                 : "+f"(d[0]), "+f"(d[1]), "+f"(d[2]), "+f"(d[3]) \
                 : "r"(a[0]), "r"(a[1]), "r"(a[2]), "r"(a[3]), \
                   "r"(b[0]), "r"(b[1]))

// ---------------------------------------------------------------------------
// GEMM-NT: C[4096,4096] = A[4096,2048] * B[4096,2048]^T + bias
// 8 warps (4M x 2N), warp tile 32x64, BK=64, 2-stage cp.async, 2 CTAs/SM.
// ---------------------------------------------------------------------------
__global__ __launch_bounds__(256, 2) void gemm_kernel(
    const float* __restrict__ bias,
    float* __restrict__ C)
{
    extern __shared__ char smem[];
    const uint32_t sb = sm_u32(smem);
    const int tid  = threadIdx.x;
    const int wid  = tid >> 5;
    const int lane = tid & 31;
    const int wm = wid >> 1;
    const int wn = wid & 1;
    const int bm = blockIdx.y * BM;
    const int bn = blockIdx.x * BN;

    const __half* gA = g_A + (size_t)bm * GK;
    const __half* gB = g_B + (size_t)bn * GK;

    const int lr = tid >> 3;
    const int lc = tid & 7;

    float acc[2][8][4];
    #pragma unroll
    for (int mi = 0; mi < 2; ++mi)
        #pragma unroll
        for (int ni = 0; ni < 8; ++ni)
            #pragma unroll
            for (int j = 0; j < 4; ++j) acc[mi][ni][j] = 0.0f;

    uint32_t s_store[2][4];
    #pragma unroll
    for (int p = 0; p < 4; ++p) {
        int r = p * 32 + lr;
        uint32_t off = (uint32_t)r * 128 + (uint32_t)((lc ^ (r & 7)) << 4);
        s_store[0][p] = sb + off;
        s_store[1][p] = sb + A_TILE_B + off;
    }

    const int a_row0 = wm * 32 + (lane & 15);
    const int a_kcb  = lane >> 4;
    const int b_n0   = wn * 64 + ((lane >> 4) << 3) + (lane & 7);
    const int b_kcb  = (lane >> 3) & 1;

    #define LOAD_STAGE(slot, k)                                                \
        do {                                                                   \
            const __half* ga = gA + (size_t)(k) * BK;                          \
            const __half* gb = gB + (size_t)(k) * BK;                          \
            const uint32_t so = (uint32_t)(slot) * STAGE_B;                    \
            _Pragma("unroll")                                                  \
            for (int p = 0; p < 4; ++p) {                                      \
                int r = p * 32 + lr;                                           \
                CP_ASYNC16(s_store[0][p] + so,                                 \
                           (uint64_t)(ga + (size_t)r * GK + lc * 8));          \
                CP_ASYNC16(s_store[1][p] + so,                                 \
                           (uint64_t)(gb + (size_t)r * GK + lc * 8));          \
            }                                                                  \
            CP_COMMIT();                                                       \
        } while (0)

    LOAD_STAGE(0, 0);

    for (int kt = 0; kt < NKT; ++kt) {
        const int s = kt & 1;
        if (kt + 1 < NKT) {
            LOAD_STAGE(s ^ 1, kt + 1);
            CP_WAIT(1);
        } else {
            CP_WAIT(0);
        }
        __syncthreads();

        const uint32_t sA = sb + (uint32_t)s * STAGE_B;
        const uint32_t sB = sA + A_TILE_B;

        #pragma unroll
        for (int k16 = 0; k16 < BK / 16; ++k16) {
            const int kc_a = k16 * 2 + a_kcb;
            const int kc_b = k16 * 2 + b_kcb;

            uint32_t a[2][4];
            #pragma unroll
            for (int mi = 0; mi < 2; ++mi) {
                int row = a_row0 + mi * 16;
                uint32_t addr = sA + (uint32_t)row * 128
                              + (uint32_t)((kc_a ^ (row & 7)) << 4);
                LDMATRIX_X4(a[mi][0], a[mi][1], a[mi][2], a[mi][3], addr);
            }
            uint32_t b[8][2];
            #pragma unroll
            for (int nj = 0; nj < 4; ++nj) {
                int n = b_n0 + nj * 16;
                uint32_t addr = sB + (uint32_t)n * 128
                              + (uint32_t)((kc_b ^ (n & 7)) << 4);
                LDMATRIX_X4(b[nj * 2][0], b[nj * 2][1],
                            b[nj * 2 + 1][0], b[nj * 2 + 1][1], addr);
            }
            #pragma unroll
            for (int mi = 0; mi < 2; ++mi)
                #pragma unroll
                for (int ni = 0; ni < 8; ++ni)
                    MMA_16816(acc[mi][ni], a[mi], b[ni]);
        }
        __syncthreads();
    }

    #pragma unroll
    for (int mi = 0; mi < 2; ++mi) {
        const int r0 = bm + wm * 32 + mi * 16 + (lane >> 2);
        #pragma unroll
        for (int ni = 0; ni < 8; ++ni) {
            const int col = bn + wn * 64 + ni * 8 + (lane & 3) * 2;
            const float b0 = __ldg(bias + col);
            const float b1 = __ldg(bias + col + 1);
            float2 v0 = make_float2(acc[mi][ni][0] + b0, acc[mi][ni][1] + b1);
            float2 v1 = make_float2(acc[mi][ni][2] + b0, acc[mi][ni][3] + b1);
            *(float2*)(C + (size_t)r0 * GN + col)       = v0;
            *(float2*)(C + (size_t)(r0 + 8) * GN + col) = v1;
        }
    }
}

// ---------------------------------------------------------------------------
// Launch
// ---------------------------------------------------------------------------
extern "C" void kernel_launch(void* const* d_in, const int* in_sizes, int n_in,
                              void* d_out, int out_size)
{
    const float* input  = (const float*)d_in[0];
    const float* weight = (const float*)d_in[1];
    const float* bias   = (const float*)d_in[2];
    const int*   hidx   = (const int*)d_in[3];
    const float* sgn    = (const float*)d_in[4];
    float* out = (float*)d_out;

    sketch_kernel<<<4096, 256>>>(input, weight, hidx, sgn);

    cudaFuncSetAttribute(gemm_kernel,
                         cudaFuncAttributeMaxDynamicSharedMemorySize, SMEM_TOTAL);
    dim3 grid(GN / BN, GM / BM);  // 32 x 32
    gemm_kernel<<<grid, 256, SMEM_TOTAL>>>(bias, out);
}